// round 7
// baseline (speedup 1.0000x reference)
#include <cuda_runtime.h>
#include <cuda_bf16.h>
#include <cstdint>
#include <math.h>

#define BATCH 4
#define CH    512
#define HW    4096
#define NG    32

static const size_t SFE = (size_t)CH * HW;

// ================= scratch (device globals) =================
__device__ float g_xn[(size_t)BATCH * CH * HW];
__device__ float g_s [(size_t)BATCH * HW * HW];

__device__ __nv_bfloat16 g_xnT_h[(size_t)BATCH * HW * CH];
__device__ __nv_bfloat16 g_xnT_l[(size_t)BATCH * HW * CH];
__device__ __nv_bfloat16 g_qT_h [(size_t)BATCH * HW * CH];
__device__ __nv_bfloat16 g_qT_l [(size_t)BATCH * HW * CH];
__device__ __nv_bfloat16 g_kT_h [(size_t)BATCH * HW * CH];
__device__ __nv_bfloat16 g_kT_l [(size_t)BATCH * HW * CH];
__device__ __nv_bfloat16 g_v_h  [(size_t)BATCH * CH * HW];
__device__ __nv_bfloat16 g_v_l  [(size_t)BATCH * CH * HW];
__device__ __nv_bfloat16 g_ot_h [(size_t)BATCH * HW * CH];
__device__ __nv_bfloat16 g_ot_l [(size_t)BATCH * HW * CH];
__device__ __nv_bfloat16 g_P_h  [(size_t)BATCH * HW * HW];
__device__ __nv_bfloat16 g_P_l  [(size_t)BATCH * HW * HW];
__device__ __nv_bfloat16 g_w_h  [(size_t)4 * CH * CH];
__device__ __nv_bfloat16 g_w_l  [(size_t)4 * CH * CH];

// ================= helpers =================
__device__ __forceinline__ uint32_t smem_u32(const void* p) {
    uint32_t a;
    asm("{ .reg .u64 t; cvta.to.shared.u64 t, %1; cvt.u32.u64 %0, t; }"
        : "=r"(a) : "l"(p));
    return a;
}
__device__ __forceinline__ uint32_t pack2(__nv_bfloat16 a, __nv_bfloat16 b) {
    return (uint32_t)__bfloat16_as_ushort(a) |
           ((uint32_t)__bfloat16_as_ushort(b) << 16);
}
__device__ __forceinline__ void split(float v, __nv_bfloat16& h, __nv_bfloat16& l) {
    h = __float2bfloat16(v);
    l = __float2bfloat16(v - __bfloat162float(h));
}

#define LDSM4(R, a) \
    asm volatile("ldmatrix.sync.aligned.m8n8.x4.shared.b16 {%0,%1,%2,%3}, [%4];" \
        : "=r"((R)[0]), "=r"((R)[1]), "=r"((R)[2]), "=r"((R)[3]) : "r"(a))

__device__ __forceinline__ void mma16816(float* d, const uint32_t* a,
                                         const uint32_t* b) {
    asm volatile(
        "mma.sync.aligned.m16n8k16.row.col.f32.bf16.bf16.f32 "
        "{%0,%1,%2,%3}, {%4,%5,%6,%7}, {%8,%9}, {%0,%1,%2,%3};"
        : "+f"(d[0]), "+f"(d[1]), "+f"(d[2]), "+f"(d[3])
        : "r"(a[0]), "r"(a[1]), "r"(a[2]), "r"(a[3]), "r"(b[0]), "r"(b[1]));
}

// smem: 4 matrices (Ah, Al, Bh, Bl), 128 rows x 32 bf16, padded to 80B rows.
#define ROWB   80
#define MATB   10240
#define STAGEB 40960
#define SM_BYTES (2 * STAGEB)

// ============================================================
// split-bf16 GEMM via mma.sync + ldmatrix.
// Ctile(128x128) = A(MxK) . B(NxK)^T ; A,B K-major bf16 hi/lo; K % 32 == 0.
// ============================================================
template<bool SPLIT, bool BROW, bool BCOL, bool RES>
__device__ __forceinline__ void tgemm(
    const __nv_bfloat16* __restrict__ Ah, const __nv_bfloat16* __restrict__ Al, int lda,
    const __nv_bfloat16* __restrict__ Bh, const __nv_bfloat16* __restrict__ Bl, int ldb,
    int K, float alpha,
    const float* __restrict__ bias_row, const float* __restrict__ bias_col,
    const float* __restrict__ res, int ldr,
    float* __restrict__ Cf, __nv_bfloat16* __restrict__ Chi,
    __nv_bfloat16* __restrict__ Clo, int ldc)
{
    extern __shared__ char smem[];
    const uint32_t sb = smem_u32(smem);
    const int tid  = threadIdx.x;
    const int wid  = tid >> 5, lane = tid & 31;
    const int mw   = wid >> 1, nw = wid & 1;          // warp tile: 32m x 64n
    const int m0   = blockIdx.y * 128, n0 = blockIdx.x * 128;
    const int C    = K >> 5;

    float acc[2][8][4];
    #pragma unroll
    for (int i = 0; i < 2; i++)
        #pragma unroll
        for (int j = 0; j < 8; j++)
            #pragma unroll
            for (int q = 0; q < 4; q++) acc[i][j][q] = 0.f;

    auto load_chunk = [&](int ck) {
        const uint32_t stage = sb + (ck & 1) * STAGEB;
        #pragma unroll
        for (int i = 0; i < 8; i++) {
            const int unit = tid + 256 * i;
            const int mat = unit >> 9;
            const int row = (unit >> 2) & 127;
            const int u   = unit & 3;
            const __nv_bfloat16* src =
                (mat == 0) ? Ah : (mat == 1) ? Al : (mat == 2) ? Bh : Bl;
            const int ld_ = (mat < 2) ? lda : ldb;
            const int r0  = (mat < 2) ? m0  : n0;
            const char* gsrc =
                (const char*)(src + (size_t)(r0 + row) * ld_ + ck * 32) + u * 16;
            const uint32_t dst = stage + mat * MATB + row * ROWB + u * 16;
            asm volatile("cp.async.cg.shared.global [%0], [%1], 16;"
                         :: "r"(dst), "l"(gsrc));
        }
        asm volatile("cp.async.commit_group;" ::: "memory");
    };

    load_chunk(0);

    const int gq = lane >> 2, qt = lane & 3;
    // ldmatrix lane address components
    const int lnA_row = lane & 15;             // row within 16-row A tile
    const int lnA_off = (lane >> 4) << 4;      // +16B for k+8 matrices
    const int lnB_row = (lane & 7) + ((lane & 16) >> 1);  // row within 16-row B pair
    const int lnB_off = (lane & 8) << 1;       // +16B for k+8 matrices

    for (int c = 0; c < C; c++) {
        if (c + 1 < C) load_chunk(c + 1);
        if (c + 1 < C) asm volatile("cp.async.wait_group 1;" ::: "memory");
        else           asm volatile("cp.async.wait_group 0;" ::: "memory");
        __syncthreads();

        const uint32_t stage = sb + (c & 1) * STAGEB;

        #pragma unroll
        for (int ks = 0; ks < 2; ks++) {
            const uint32_t ko = ks * 32;       // 16 elems = 32 B

            uint32_t ah[2][4], al[2][4];
            #pragma unroll
            for (int mt = 0; mt < 2; mt++) {
                const uint32_t aAddr = stage +
                    (mw * 32 + mt * 16 + lnA_row) * ROWB + ko + lnA_off;
                LDSM4(ah[mt], aAddr);
                LDSM4(al[mt], aAddr + MATB);
            }

            #pragma unroll
            for (int ntp = 0; ntp < 4; ntp++) {
                const uint32_t bAddr = stage + 2 * MATB +
                    (nw * 64 + ntp * 16 + lnB_row) * ROWB + ko + lnB_off;
                uint32_t bh[4], bl[4];
                LDSM4(bh, bAddr);
                LDSM4(bl, bAddr + MATB);
                #pragma unroll
                for (int half = 0; half < 2; half++) {
                    const int nt = ntp * 2 + half;
                    #pragma unroll
                    for (int mt = 0; mt < 2; mt++) {
                        mma16816(acc[mt][nt], ah[mt], bh + half * 2);
                        mma16816(acc[mt][nt], ah[mt], bl + half * 2);
                        mma16816(acc[mt][nt], al[mt], bh + half * 2);
                    }
                }
            }
        }
        __syncthreads();
    }

    // ---- epilogue ----
    #pragma unroll
    for (int mt = 0; mt < 2; mt++) {
        const int mA = m0 + mw * 32 + mt * 16 + gq;
        #pragma unroll
        for (int half = 0; half < 2; half++) {
            const int m = mA + half * 8;
            const float br = BROW ? bias_row[m] : 0.f;
            #pragma unroll
            for (int nt = 0; nt < 8; nt++) {
                const int n = n0 + nw * 64 + nt * 8 + qt * 2;
                float vx = acc[mt][nt][half * 2 + 0] * alpha + br;
                float vy = acc[mt][nt][half * 2 + 1] * alpha + br;
                if (BCOL) { vx += bias_col[n]; vy += bias_col[n + 1]; }
                if (RES) {
                    const float* rp = res + (size_t)m * ldr + n;
                    vx += rp[0]; vy += rp[1];
                }
                if (SPLIT) {
                    __nv_bfloat16 h0, h1, l0, l1;
                    split(vx, h0, l0); split(vy, h1, l1);
                    *(uint32_t*)(Chi + (size_t)m * ldc + n) = pack2(h0, h1);
                    *(uint32_t*)(Clo + (size_t)m * ldc + n) = pack2(l0, l1);
                } else {
                    float2 o = {vx, vy};
                    *(float2*)(Cf + (size_t)m * ldc + n) = o;
                }
            }
        }
    }
}

// ================= wrapper kernels =================

__global__ __launch_bounds__(256, 1) void tg_qk(
    const float* __restrict__ bq, const float* __restrict__ bk)
{
    const int b = blockIdx.z >> 1, s = blockIdx.z & 1;
    const __nv_bfloat16* Wh = g_w_h + (size_t)s * CH * CH;
    const __nv_bfloat16* Wl = g_w_l + (size_t)s * CH * CH;
    __nv_bfloat16* Ch = (s == 0 ? g_qT_h : g_kT_h) + (size_t)b * HW * CH;
    __nv_bfloat16* Cl = (s == 0 ? g_qT_l : g_kT_l) + (size_t)b * HW * CH;
    tgemm<true, false, true, false>(
        g_xnT_h + (size_t)b * HW * CH, g_xnT_l + (size_t)b * HW * CH, CH,
        Wh, Wl, CH, CH, 1.f, nullptr, (s == 0 ? bq : bk), nullptr, 0,
        nullptr, Ch, Cl, CH);
}

__global__ __launch_bounds__(256, 1) void tg_v(const float* __restrict__ bv)
{
    const int b = blockIdx.z;
    tgemm<true, true, false, false>(
        g_w_h + (size_t)2 * CH * CH, g_w_l + (size_t)2 * CH * CH, CH,
        g_xnT_h + (size_t)b * HW * CH, g_xnT_l + (size_t)b * HW * CH, CH,
        CH, 1.f, bv, nullptr, nullptr, 0,
        nullptr, g_v_h + (size_t)b * CH * HW, g_v_l + (size_t)b * CH * HW, HW);
}

__global__ __launch_bounds__(256, 1) void tg_score()
{
    const int b = blockIdx.z;
    tgemm<false, false, false, false>(
        g_qT_h + (size_t)b * HW * CH, g_qT_l + (size_t)b * HW * CH, CH,
        g_kT_h + (size_t)b * HW * CH, g_kT_l + (size_t)b * HW * CH, CH,
        CH, 0.044194173824159216f, nullptr, nullptr, nullptr, 0,
        g_s + (size_t)b * HW * HW, nullptr, nullptr, HW);
}

__global__ __launch_bounds__(256, 1) void tg_av()
{
    const int b = blockIdx.z;
    tgemm<true, false, false, false>(
        g_P_h + (size_t)b * HW * HW, g_P_l + (size_t)b * HW * HW, HW,
        g_v_h + (size_t)b * CH * HW, g_v_l + (size_t)b * CH * HW, HW,
        HW, 1.f, nullptr, nullptr, nullptr, 0,
        nullptr, g_ot_h + (size_t)b * HW * CH, g_ot_l + (size_t)b * HW * CH, CH);
}

__global__ __launch_bounds__(256, 1) void tg_out(
    const float* __restrict__ bo, const float* __restrict__ x,
    float* __restrict__ out)
{
    const int b = blockIdx.z;
    tgemm<false, true, false, true>(
        g_w_h + (size_t)3 * CH * CH, g_w_l + (size_t)3 * CH * CH, CH,
        g_ot_h + (size_t)b * HW * CH, g_ot_l + (size_t)b * HW * CH, CH,
        CH, 1.f, bo, nullptr, x + (size_t)b * SFE, HW,
        out + (size_t)b * SFE, nullptr, nullptr, HW);
}

// ================= GroupNorm =================
__global__ __launch_bounds__(256) void gn_kernel(
    const float* __restrict__ x, const float* __restrict__ gamma,
    const float* __restrict__ beta)
{
    const int bg = blockIdx.x;
    const int CPG = CH / NG;
    const size_t base = (size_t)bg * CPG * HW;
    const int n = CPG * HW;
    const float4* xv = (const float4*)(x + base);
    float4* yv = (float4*)(g_xn + base);
    const int t = threadIdx.x;

    float s = 0.f, ss = 0.f;
    for (int i = t; i < n / 4; i += 256) {
        float4 v = xv[i];
        s  += v.x + v.y + v.z + v.w;
        ss += v.x*v.x + v.y*v.y + v.z*v.z + v.w*v.w;
    }
    __shared__ float sh[64];
    #pragma unroll
    for (int o = 16; o > 0; o >>= 1) {
        s  += __shfl_xor_sync(~0u, s, o);
        ss += __shfl_xor_sync(~0u, ss, o);
    }
    const int warp = t >> 5, lane = t & 31;
    if (lane == 0) { sh[warp] = s; sh[32 + warp] = ss; }
    __syncthreads();
    if (warp == 0) {
        float a = (lane < 8) ? sh[lane] : 0.f;
        float b = (lane < 8) ? sh[32 + lane] : 0.f;
        #pragma unroll
        for (int o = 4; o > 0; o >>= 1) {
            a += __shfl_xor_sync(~0u, a, o);
            b += __shfl_xor_sync(~0u, b, o);
        }
        if (lane == 0) { sh[0] = a; sh[1] = b; }
    }
    __syncthreads();
    const float mean = sh[0] / n;
    const float var  = sh[1] / n - mean * mean;
    const float inv  = rsqrtf(var + 1e-6f);
    const int gbase = (bg % NG) * CPG;

    for (int i = t; i < n / 4; i += 256) {
        int ch = i / (HW / 4);
        float ga = gamma[gbase + ch] * inv;
        float be = beta[gbase + ch];
        float4 v = xv[i];
        v.x = (v.x - mean) * ga + be;
        v.y = (v.y - mean) * ga + be;
        v.z = (v.z - mean) * ga + be;
        v.w = (v.w - mean) * ga + be;
        yv[i] = v;
    }
}

// ================= transpose + split =================
__global__ __launch_bounds__(256) void xpose_kernel()
{
    __shared__ float t[32][33];
    const int b = blockIdx.z;
    const int i0 = blockIdx.x * 32, c0 = blockIdx.y * 32;
    const int tx = threadIdx.x & 31, ty = threadIdx.x >> 5;
    const float* src = g_xn + (size_t)b * SFE;
    #pragma unroll
    for (int j = 0; j < 4; j++)
        t[ty + 8*j][tx] = src[(size_t)(c0 + ty + 8*j) * HW + i0 + tx];
    __syncthreads();
    #pragma unroll
    for (int j = 0; j < 4; j++) {
        float v = t[tx][ty + 8*j];
        __nv_bfloat16 h, l; split(v, h, l);
        size_t d = (size_t)b * HW * CH + (size_t)(i0 + ty + 8*j) * CH + c0 + tx;
        g_xnT_h[d] = h; g_xnT_l[d] = l;
    }
}

// ================= weight split =================
__global__ __launch_bounds__(256) void wconv_kernel(
    const float* __restrict__ wq, const float* __restrict__ wk,
    const float* __restrict__ wv, const float* __restrict__ wo)
{
    const size_t idx = (size_t)blockIdx.x * 256 + threadIdx.x;
    const int which = (int)(idx >> 18);
    const size_t off = idx & ((1 << 18) - 1);
    const float* w = (which == 0) ? wq : (which == 1) ? wk : (which == 2) ? wv : wo;
    __nv_bfloat16 h, l; split(w[off], h, l);
    g_w_h[idx] = h; g_w_l[idx] = l;
}

// ================= softmax -> P hi/lo =================
__global__ __launch_bounds__(256) void softmax_kernel()
{
    const size_t row = blockIdx.x;
    const float4* pv = (const float4*)(g_s + row * HW);
    __nv_bfloat16* ph = g_P_h + row * HW;
    __nv_bfloat16* pl = g_P_l + row * HW;
    const int t = threadIdx.x;
    float4 v[4];
    float mx = -1e30f;
    #pragma unroll
    for (int j = 0; j < 4; j++) {
        v[j] = pv[t + 256 * j];
        mx = fmaxf(mx, fmaxf(fmaxf(v[j].x, v[j].y), fmaxf(v[j].z, v[j].w)));
    }
    __shared__ float sh[8];
    #pragma unroll
    for (int o = 16; o > 0; o >>= 1) mx = fmaxf(mx, __shfl_xor_sync(~0u, mx, o));
    if ((t & 31) == 0) sh[t >> 5] = mx;
    __syncthreads();
    const float m0 = fmaxf(fmaxf(fmaxf(sh[0], sh[1]), fmaxf(sh[2], sh[3])),
                           fmaxf(fmaxf(sh[4], sh[5]), fmaxf(sh[6], sh[7])));
    __syncthreads();
    float sum = 0.f;
    #pragma unroll
    for (int j = 0; j < 4; j++) {
        v[j].x = __expf(v[j].x - m0);
        v[j].y = __expf(v[j].y - m0);
        v[j].z = __expf(v[j].z - m0);
        v[j].w = __expf(v[j].w - m0);
        sum += v[j].x + v[j].y + v[j].z + v[j].w;
    }
    #pragma unroll
    for (int o = 16; o > 0; o >>= 1) sum += __shfl_xor_sync(~0u, sum, o);
    if ((t & 31) == 0) sh[t >> 5] = sum;
    __syncthreads();
    const float tot = sh[0]+sh[1]+sh[2]+sh[3]+sh[4]+sh[5]+sh[6]+sh[7];
    const float inv = 1.f / tot;
    #pragma unroll
    for (int j = 0; j < 4; j++) {
        float4 e = v[j];
        e.x *= inv; e.y *= inv; e.z *= inv; e.w *= inv;
        __nv_bfloat16 h0,h1,h2,h3,l0,l1,l2,l3;
        split(e.x,h0,l0); split(e.y,h1,l1); split(e.z,h2,l2); split(e.w,h3,l3);
        const int eo = (t + 256 * j) * 4;
        uint2 hv = { pack2(h0,h1), pack2(h2,h3) };
        uint2 lv = { pack2(l0,l1), pack2(l2,l3) };
        *(uint2*)(ph + eo) = hv;
        *(uint2*)(pl + eo) = lv;
    }
}

// ============================================================
extern "C" void kernel_launch(void* const* d_in, const int* in_sizes, int n_in,
                              void* d_out, int out_size)
{
    const float* x   = (const float*)d_in[0];
    const float* gnw = (const float*)d_in[1];
    const float* gnb = (const float*)d_in[2];
    const float* wq  = (const float*)d_in[3];
    const float* bq  = (const float*)d_in[4];
    const float* wk  = (const float*)d_in[5];
    const float* bk  = (const float*)d_in[6];
    const float* wv  = (const float*)d_in[7];
    const float* bv  = (const float*)d_in[8];
    const float* wo  = (const float*)d_in[9];
    const float* bo  = (const float*)d_in[10];
    float* out = (float*)d_out;

    cudaFuncSetAttribute(tg_qk,    cudaFuncAttributeMaxDynamicSharedMemorySize, SM_BYTES);
    cudaFuncSetAttribute(tg_v,     cudaFuncAttributeMaxDynamicSharedMemorySize, SM_BYTES);
    cudaFuncSetAttribute(tg_score, cudaFuncAttributeMaxDynamicSharedMemorySize, SM_BYTES);
    cudaFuncSetAttribute(tg_av,    cudaFuncAttributeMaxDynamicSharedMemorySize, SM_BYTES);
    cudaFuncSetAttribute(tg_out,   cudaFuncAttributeMaxDynamicSharedMemorySize, SM_BYTES);

    gn_kernel<<<BATCH * NG, 256>>>(x, gnw, gnb);

    dim3 gx(HW / 32, CH / 32, BATCH);
    xpose_kernel<<<gx, 256>>>();

    wconv_kernel<<<4 * CH * CH / 256, 256>>>(wq, wk, wv, wo);

    dim3 gqk(CH / 128, HW / 128, BATCH * 2);
    tg_qk<<<gqk, 256, SM_BYTES>>>(bq, bk);

    dim3 gv(HW / 128, CH / 128, BATCH);
    tg_v<<<gv, 256, SM_BYTES>>>(bv);

    dim3 gs(HW / 128, HW / 128, BATCH);
    tg_score<<<gs, 256, SM_BYTES>>>();

    softmax_kernel<<<BATCH * HW, 256>>>();

    dim3 ga(CH / 128, HW / 128, BATCH);
    tg_av<<<ga, 256, SM_BYTES>>>();

    dim3 go(HW / 128, CH / 128, BATCH);
    tg_out<<<go, 256, SM_BYTES>>>(bo, x, out);
}

// round 8
// speedup vs baseline: 1.0056x; 1.0056x over previous
#include <cuda_runtime.h>
#include <cuda_bf16.h>
#include <cstdint>
#include <math.h>

#define BATCH 4
#define CH    512
#define HW    4096
#define NG    32

static const size_t SFE = (size_t)CH * HW;

// ================= scratch (device globals) =================
__device__ float g_xn[(size_t)BATCH * CH * HW];
__device__ float g_s [(size_t)BATCH * HW * HW];

__device__ __nv_bfloat16 g_xnT_h[(size_t)BATCH * HW * CH];
__device__ __nv_bfloat16 g_xnT_l[(size_t)BATCH * HW * CH];
__device__ __nv_bfloat16 g_qT_h [(size_t)BATCH * HW * CH];
__device__ __nv_bfloat16 g_qT_l [(size_t)BATCH * HW * CH];
__device__ __nv_bfloat16 g_kT_h [(size_t)BATCH * HW * CH];
__device__ __nv_bfloat16 g_kT_l [(size_t)BATCH * HW * CH];
__device__ __nv_bfloat16 g_v_h  [(size_t)BATCH * CH * HW];
__device__ __nv_bfloat16 g_v_l  [(size_t)BATCH * CH * HW];
__device__ __nv_bfloat16 g_ot_h [(size_t)BATCH * HW * CH];
__device__ __nv_bfloat16 g_ot_l [(size_t)BATCH * HW * CH];
__device__ __nv_bfloat16 g_P_h  [(size_t)BATCH * HW * HW];
__device__ __nv_bfloat16 g_P_l  [(size_t)BATCH * HW * HW];
__device__ __nv_bfloat16 g_w_h  [(size_t)4 * CH * CH];
__device__ __nv_bfloat16 g_w_l  [(size_t)4 * CH * CH];

// ================= helpers =================
__device__ __forceinline__ uint32_t smem_u32(const void* p) {
    uint32_t a;
    asm("{ .reg .u64 t; cvta.to.shared.u64 t, %1; cvt.u32.u64 %0, t; }"
        : "=r"(a) : "l"(p));
    return a;
}
__device__ __forceinline__ uint32_t pack2(__nv_bfloat16 a, __nv_bfloat16 b) {
    return (uint32_t)__bfloat16_as_ushort(a) |
           ((uint32_t)__bfloat16_as_ushort(b) << 16);
}
__device__ __forceinline__ void split(float v, __nv_bfloat16& h, __nv_bfloat16& l) {
    h = __float2bfloat16(v);
    l = __float2bfloat16(v - __bfloat162float(h));
}

#define LDSM4(R, a) \
    asm volatile("ldmatrix.sync.aligned.m8n8.x4.shared.b16 {%0,%1,%2,%3}, [%4];" \
        : "=r"((R)[0]), "=r"((R)[1]), "=r"((R)[2]), "=r"((R)[3]) : "r"(a))

__device__ __forceinline__ void mma16816(float* d, const uint32_t* a,
                                         const uint32_t* b) {
    asm volatile(
        "mma.sync.aligned.m16n8k16.row.col.f32.bf16.bf16.f32 "
        "{%0,%1,%2,%3}, {%4,%5,%6,%7}, {%8,%9}, {%0,%1,%2,%3};"
        : "+f"(d[0]), "+f"(d[1]), "+f"(d[2]), "+f"(d[3])
        : "r"(a[0]), "r"(a[1]), "r"(a[2]), "r"(a[3]), "r"(b[0]), "r"(b[1]));
}

// smem: 4 matrices (Ah, Al, Bh, Bl), 128 rows x 32 bf16, padded to 80B rows.
#define ROWB   80
#define MATB   10240
#define STAGEB 40960
#define SM_BYTES (2 * STAGEB)
#define THREADS 512

// ============================================================
// split-bf16 GEMM via mma.sync + ldmatrix. 16 warps, warp tile 32m x 32n.
// Ctile(128x128) = A(MxK) . B(NxK)^T ; A,B K-major bf16 hi/lo; K % 32 == 0.
// ============================================================
template<bool SPLIT, bool BROW, bool BCOL, bool RES>
__device__ __forceinline__ void tgemm(
    const __nv_bfloat16* __restrict__ Ah, const __nv_bfloat16* __restrict__ Al, int lda,
    const __nv_bfloat16* __restrict__ Bh, const __nv_bfloat16* __restrict__ Bl, int ldb,
    int K, float alpha,
    const float* __restrict__ bias_row, const float* __restrict__ bias_col,
    const float* __restrict__ res, int ldr,
    float* __restrict__ Cf, __nv_bfloat16* __restrict__ Chi,
    __nv_bfloat16* __restrict__ Clo, int ldc)
{
    extern __shared__ char smem[];
    const uint32_t sb = smem_u32(smem);
    const int tid  = threadIdx.x;
    const int wid  = tid >> 5, lane = tid & 31;
    const int mw   = wid >> 2, nw = wid & 3;          // 4x4 warp grid, 32m x 32n
    const int m0   = blockIdx.y * 128, n0 = blockIdx.x * 128;
    const int C    = K >> 5;

    float acc[2][4][4];
    #pragma unroll
    for (int i = 0; i < 2; i++)
        #pragma unroll
        for (int j = 0; j < 4; j++)
            #pragma unroll
            for (int q = 0; q < 4; q++) acc[i][j][q] = 0.f;

    auto load_chunk = [&](int ck) {
        const uint32_t stage = sb + (ck & 1) * STAGEB;
        #pragma unroll
        for (int i = 0; i < 4; i++) {
            const int unit = tid + THREADS * i;       // 2048 units of 16B
            const int mat = unit >> 9;
            const int row = (unit >> 2) & 127;
            const int u   = unit & 3;
            const __nv_bfloat16* src =
                (mat == 0) ? Ah : (mat == 1) ? Al : (mat == 2) ? Bh : Bl;
            const int ld_ = (mat < 2) ? lda : ldb;
            const int r0  = (mat < 2) ? m0  : n0;
            const char* gsrc =
                (const char*)(src + (size_t)(r0 + row) * ld_ + ck * 32) + u * 16;
            const uint32_t dst = stage + mat * MATB + row * ROWB + u * 16;
            asm volatile("cp.async.cg.shared.global [%0], [%1], 16;"
                         :: "r"(dst), "l"(gsrc));
        }
        asm volatile("cp.async.commit_group;" ::: "memory");
    };

    load_chunk(0);

    const int gq = lane >> 2, qt = lane & 3;
    const int lnA_row = lane & 15;
    const int lnA_off = (lane >> 4) << 4;
    const int lnB_row = (lane & 7) + ((lane & 16) >> 1);
    const int lnB_off = (lane & 8) << 1;

    for (int c = 0; c < C; c++) {
        if (c + 1 < C) load_chunk(c + 1);
        if (c + 1 < C) asm volatile("cp.async.wait_group 1;" ::: "memory");
        else           asm volatile("cp.async.wait_group 0;" ::: "memory");
        __syncthreads();

        const uint32_t stage = sb + (c & 1) * STAGEB;

        #pragma unroll
        for (int ks = 0; ks < 2; ks++) {
            const uint32_t ko = ks * 32;

            uint32_t ah[2][4], al[2][4];
            #pragma unroll
            for (int mt = 0; mt < 2; mt++) {
                const uint32_t aAddr = stage +
                    (mw * 32 + mt * 16 + lnA_row) * ROWB + ko + lnA_off;
                LDSM4(ah[mt], aAddr);
                LDSM4(al[mt], aAddr + MATB);
            }

            #pragma unroll
            for (int p = 0; p < 2; p++) {
                const uint32_t bAddr = stage + 2 * MATB +
                    (nw * 32 + p * 16 + lnB_row) * ROWB + ko + lnB_off;
                uint32_t bh[4], bl[4];
                LDSM4(bh, bAddr);
                LDSM4(bl, bAddr + MATB);
                #pragma unroll
                for (int half = 0; half < 2; half++) {
                    const int nt = p * 2 + half;
                    #pragma unroll
                    for (int mt = 0; mt < 2; mt++) {
                        mma16816(acc[mt][nt], ah[mt], bh + half * 2);
                        mma16816(acc[mt][nt], ah[mt], bl + half * 2);
                        mma16816(acc[mt][nt], al[mt], bh + half * 2);
                    }
                }
            }
        }
        __syncthreads();
    }

    // ---- epilogue ----
    #pragma unroll
    for (int mt = 0; mt < 2; mt++) {
        const int mA = m0 + mw * 32 + mt * 16 + gq;
        #pragma unroll
        for (int half = 0; half < 2; half++) {
            const int m = mA + half * 8;
            const float br = BROW ? bias_row[m] : 0.f;
            #pragma unroll
            for (int nt = 0; nt < 4; nt++) {
                const int n = n0 + nw * 32 + nt * 8 + qt * 2;
                float vx = acc[mt][nt][half * 2 + 0] * alpha + br;
                float vy = acc[mt][nt][half * 2 + 1] * alpha + br;
                if (BCOL) { vx += bias_col[n]; vy += bias_col[n + 1]; }
                if (RES) {
                    const float* rp = res + (size_t)m * ldr + n;
                    vx += rp[0]; vy += rp[1];
                }
                if (SPLIT) {
                    __nv_bfloat16 h0, h1, l0, l1;
                    split(vx, h0, l0); split(vy, h1, l1);
                    *(uint32_t*)(Chi + (size_t)m * ldc + n) = pack2(h0, h1);
                    *(uint32_t*)(Clo + (size_t)m * ldc + n) = pack2(l0, l1);
                } else {
                    float2 o = {vx, vy};
                    *(float2*)(Cf + (size_t)m * ldc + n) = o;
                }
            }
        }
    }
}

// ================= wrapper kernels =================

__global__ __launch_bounds__(THREADS, 1) void tg_qk(
    const float* __restrict__ bq, const float* __restrict__ bk)
{
    const int b = blockIdx.z >> 1, s = blockIdx.z & 1;
    const __nv_bfloat16* Wh = g_w_h + (size_t)s * CH * CH;
    const __nv_bfloat16* Wl = g_w_l + (size_t)s * CH * CH;
    __nv_bfloat16* Ch = (s == 0 ? g_qT_h : g_kT_h) + (size_t)b * HW * CH;
    __nv_bfloat16* Cl = (s == 0 ? g_qT_l : g_kT_l) + (size_t)b * HW * CH;
    tgemm<true, false, true, false>(
        g_xnT_h + (size_t)b * HW * CH, g_xnT_l + (size_t)b * HW * CH, CH,
        Wh, Wl, CH, CH, 1.f, nullptr, (s == 0 ? bq : bk), nullptr, 0,
        nullptr, Ch, Cl, CH);
}

__global__ __launch_bounds__(THREADS, 1) void tg_v(const float* __restrict__ bv)
{
    const int b = blockIdx.z;
    tgemm<true, true, false, false>(
        g_w_h + (size_t)2 * CH * CH, g_w_l + (size_t)2 * CH * CH, CH,
        g_xnT_h + (size_t)b * HW * CH, g_xnT_l + (size_t)b * HW * CH, CH,
        CH, 1.f, bv, nullptr, nullptr, 0,
        nullptr, g_v_h + (size_t)b * CH * HW, g_v_l + (size_t)b * CH * HW, HW);
}

__global__ __launch_bounds__(THREADS, 1) void tg_score()
{
    const int b = blockIdx.z;
    tgemm<false, false, false, false>(
        g_qT_h + (size_t)b * HW * CH, g_qT_l + (size_t)b * HW * CH, CH,
        g_kT_h + (size_t)b * HW * CH, g_kT_l + (size_t)b * HW * CH, CH,
        CH, 0.044194173824159216f, nullptr, nullptr, nullptr, 0,
        g_s + (size_t)b * HW * HW, nullptr, nullptr, HW);
}

__global__ __launch_bounds__(THREADS, 1) void tg_av()
{
    const int b = blockIdx.z;
    tgemm<true, false, false, false>(
        g_P_h + (size_t)b * HW * HW, g_P_l + (size_t)b * HW * HW, HW,
        g_v_h + (size_t)b * CH * HW, g_v_l + (size_t)b * CH * HW, HW,
        HW, 1.f, nullptr, nullptr, nullptr, 0,
        nullptr, g_ot_h + (size_t)b * HW * CH, g_ot_l + (size_t)b * HW * CH, CH);
}

__global__ __launch_bounds__(THREADS, 1) void tg_out(
    const float* __restrict__ bo, const float* __restrict__ x,
    float* __restrict__ out)
{
    const int b = blockIdx.z;
    tgemm<false, true, false, true>(
        g_w_h + (size_t)3 * CH * CH, g_w_l + (size_t)3 * CH * CH, CH,
        g_ot_h + (size_t)b * HW * CH, g_ot_l + (size_t)b * HW * CH, CH,
        CH, 1.f, bo, nullptr, x + (size_t)b * SFE, HW,
        out + (size_t)b * SFE, nullptr, nullptr, HW);
}

// ================= GroupNorm =================
__global__ __launch_bounds__(256) void gn_kernel(
    const float* __restrict__ x, const float* __restrict__ gamma,
    const float* __restrict__ beta)
{
    const int bg = blockIdx.x;
    const int CPG = CH / NG;
    const size_t base = (size_t)bg * CPG * HW;
    const int n = CPG * HW;
    const float4* xv = (const float4*)(x + base);
    float4* yv = (float4*)(g_xn + base);
    const int t = threadIdx.x;

    float s = 0.f, ss = 0.f;
    for (int i = t; i < n / 4; i += 256) {
        float4 v = xv[i];
        s  += v.x + v.y + v.z + v.w;
        ss += v.x*v.x + v.y*v.y + v.z*v.z + v.w*v.w;
    }
    __shared__ float sh[64];
    #pragma unroll
    for (int o = 16; o > 0; o >>= 1) {
        s  += __shfl_xor_sync(~0u, s, o);
        ss += __shfl_xor_sync(~0u, ss, o);
    }
    const int warp = t >> 5, lane = t & 31;
    if (lane == 0) { sh[warp] = s; sh[32 + warp] = ss; }
    __syncthreads();
    if (warp == 0) {
        float a = (lane < 8) ? sh[lane] : 0.f;
        float b = (lane < 8) ? sh[32 + lane] : 0.f;
        #pragma unroll
        for (int o = 4; o > 0; o >>= 1) {
            a += __shfl_xor_sync(~0u, a, o);
            b += __shfl_xor_sync(~0u, b, o);
        }
        if (lane == 0) { sh[0] = a; sh[1] = b; }
    }
    __syncthreads();
    const float mean = sh[0] / n;
    const float var  = sh[1] / n - mean * mean;
    const float inv  = rsqrtf(var + 1e-6f);
    const int gbase = (bg % NG) * CPG;

    for (int i = t; i < n / 4; i += 256) {
        int ch = i / (HW / 4);
        float ga = gamma[gbase + ch] * inv;
        float be = beta[gbase + ch];
        float4 v = xv[i];
        v.x = (v.x - mean) * ga + be;
        v.y = (v.y - mean) * ga + be;
        v.z = (v.z - mean) * ga + be;
        v.w = (v.w - mean) * ga + be;
        yv[i] = v;
    }
}

// ================= transpose + split =================
__global__ __launch_bounds__(256) void xpose_kernel()
{
    __shared__ float t[32][33];
    const int b = blockIdx.z;
    const int i0 = blockIdx.x * 32, c0 = blockIdx.y * 32;
    const int tx = threadIdx.x & 31, ty = threadIdx.x >> 5;
    const float* src = g_xn + (size_t)b * SFE;
    #pragma unroll
    for (int j = 0; j < 4; j++)
        t[ty + 8*j][tx] = src[(size_t)(c0 + ty + 8*j) * HW + i0 + tx];
    __syncthreads();
    #pragma unroll
    for (int j = 0; j < 4; j++) {
        float v = t[tx][ty + 8*j];
        __nv_bfloat16 h, l; split(v, h, l);
        size_t d = (size_t)b * HW * CH + (size_t)(i0 + ty + 8*j) * CH + c0 + tx;
        g_xnT_h[d] = h; g_xnT_l[d] = l;
    }
}

// ================= weight split =================
__global__ __launch_bounds__(256) void wconv_kernel(
    const float* __restrict__ wq, const float* __restrict__ wk,
    const float* __restrict__ wv, const float* __restrict__ wo)
{
    const size_t idx = (size_t)blockIdx.x * 256 + threadIdx.x;
    const int which = (int)(idx >> 18);
    const size_t off = idx & ((1 << 18) - 1);
    const float* w = (which == 0) ? wq : (which == 1) ? wk : (which == 2) ? wv : wo;
    __nv_bfloat16 h, l; split(w[off], h, l);
    g_w_h[idx] = h; g_w_l[idx] = l;
}

// ================= softmax -> P hi/lo =================
__global__ __launch_bounds__(256) void softmax_kernel()
{
    const size_t row = blockIdx.x;
    const float4* pv = (const float4*)(g_s + row * HW);
    __nv_bfloat16* ph = g_P_h + row * HW;
    __nv_bfloat16* pl = g_P_l + row * HW;
    const int t = threadIdx.x;
    float4 v[4];
    float mx = -1e30f;
    #pragma unroll
    for (int j = 0; j < 4; j++) {
        v[j] = pv[t + 256 * j];
        mx = fmaxf(mx, fmaxf(fmaxf(v[j].x, v[j].y), fmaxf(v[j].z, v[j].w)));
    }
    __shared__ float sh[8];
    #pragma unroll
    for (int o = 16; o > 0; o >>= 1) mx = fmaxf(mx, __shfl_xor_sync(~0u, mx, o));
    if ((t & 31) == 0) sh[t >> 5] = mx;
    __syncthreads();
    const float m0 = fmaxf(fmaxf(fmaxf(sh[0], sh[1]), fmaxf(sh[2], sh[3])),
                           fmaxf(fmaxf(sh[4], sh[5]), fmaxf(sh[6], sh[7])));
    __syncthreads();
    float sum = 0.f;
    #pragma unroll
    for (int j = 0; j < 4; j++) {
        v[j].x = __expf(v[j].x - m0);
        v[j].y = __expf(v[j].y - m0);
        v[j].z = __expf(v[j].z - m0);
        v[j].w = __expf(v[j].w - m0);
        sum += v[j].x + v[j].y + v[j].z + v[j].w;
    }
    #pragma unroll
    for (int o = 16; o > 0; o >>= 1) sum += __shfl_xor_sync(~0u, sum, o);
    if ((t & 31) == 0) sh[t >> 5] = sum;
    __syncthreads();
    const float tot = sh[0]+sh[1]+sh[2]+sh[3]+sh[4]+sh[5]+sh[6]+sh[7];
    const float inv = 1.f / tot;
    #pragma unroll
    for (int j = 0; j < 4; j++) {
        float4 e = v[j];
        e.x *= inv; e.y *= inv; e.z *= inv; e.w *= inv;
        __nv_bfloat16 h0,h1,h2,h3,l0,l1,l2,l3;
        split(e.x,h0,l0); split(e.y,h1,l1); split(e.z,h2,l2); split(e.w,h3,l3);
        const int eo = (t + 256 * j) * 4;
        uint2 hv = { pack2(h0,h1), pack2(h2,h3) };
        uint2 lv = { pack2(l0,l1), pack2(l2,l3) };
        *(uint2*)(ph + eo) = hv;
        *(uint2*)(pl + eo) = lv;
    }
}

// ============================================================
extern "C" void kernel_launch(void* const* d_in, const int* in_sizes, int n_in,
                              void* d_out, int out_size)
{
    const float* x   = (const float*)d_in[0];
    const float* gnw = (const float*)d_in[1];
    const float* gnb = (const float*)d_in[2];
    const float* wq  = (const float*)d_in[3];
    const float* bq  = (const float*)d_in[4];
    const float* wk  = (const float*)d_in[5];
    const float* bk  = (const float*)d_in[6];
    const float* wv  = (const float*)d_in[7];
    const float* bv  = (const float*)d_in[8];
    const float* wo  = (const float*)d_in[9];
    const float* bo  = (const float*)d_in[10];
    float* out = (float*)d_out;

    cudaFuncSetAttribute(tg_qk,    cudaFuncAttributeMaxDynamicSharedMemorySize, SM_BYTES);
    cudaFuncSetAttribute(tg_v,     cudaFuncAttributeMaxDynamicSharedMemorySize, SM_BYTES);
    cudaFuncSetAttribute(tg_score, cudaFuncAttributeMaxDynamicSharedMemorySize, SM_BYTES);
    cudaFuncSetAttribute(tg_av,    cudaFuncAttributeMaxDynamicSharedMemorySize, SM_BYTES);
    cudaFuncSetAttribute(tg_out,   cudaFuncAttributeMaxDynamicSharedMemorySize, SM_BYTES);

    gn_kernel<<<BATCH * NG, 256>>>(x, gnw, gnb);

    dim3 gx(HW / 32, CH / 32, BATCH);
    xpose_kernel<<<gx, 256>>>();

    wconv_kernel<<<4 * CH * CH / 256, 256>>>(wq, wk, wv, wo);

    dim3 gqk(CH / 128, HW / 128, BATCH * 2);
    tg_qk<<<gqk, THREADS, SM_BYTES>>>(bq, bk);

    dim3 gv(HW / 128, CH / 128, BATCH);
    tg_v<<<gv, THREADS, SM_BYTES>>>(bv);

    dim3 gs(HW / 128, HW / 128, BATCH);
    tg_score<<<gs, THREADS, SM_BYTES>>>();

    softmax_kernel<<<BATCH * HW, 256>>>();

    dim3 ga(CH / 128, HW / 128, BATCH);
    tg_av<<<ga, THREADS, SM_BYTES>>>();

    dim3 go(HW / 128, CH / 128, BATCH);
    tg_out<<<go, THREADS, SM_BYTES>>>(bo, x, out);
}

// round 9
// speedup vs baseline: 1.7565x; 1.7467x over previous
#include <cuda_runtime.h>
#include <cuda_bf16.h>
#include <cuda_fp16.h>
#include <cstdint>
#include <math.h>

#define BATCH 4
#define CH    512
#define HW    4096
#define NG    32

static const size_t SFE = (size_t)CH * HW;

// ================= scratch (device globals) =================
__device__ float g_xn[(size_t)BATCH * CH * HW];
__device__ float g_s [(size_t)BATCH * HW * HW];

__device__ __nv_bfloat16 g_xnT_h[(size_t)BATCH * HW * CH];   // (i,c)
__device__ __nv_bfloat16 g_xnT_l[(size_t)BATCH * HW * CH];
__device__ __half        g_q16  [(size_t)BATCH * HW * CH];   // (i,c) fp16
__device__ __half        g_k16  [(size_t)BATCH * HW * CH];   // (i,c) fp16
__device__ __half        g_v16  [(size_t)BATCH * CH * HW];   // (c,i) fp16
__device__ __half        g_P16  [(size_t)BATCH * HW * HW];   // probs fp16
__device__ __nv_bfloat16 g_ot_h [(size_t)BATCH * HW * CH];   // (i,c)
__device__ __nv_bfloat16 g_ot_l [(size_t)BATCH * HW * CH];
__device__ __nv_bfloat16 g_w_h  [(size_t)4 * CH * CH];
__device__ __nv_bfloat16 g_w_l  [(size_t)4 * CH * CH];

// ================= helpers =================
__device__ __forceinline__ uint32_t smem_u32(const void* p) {
    uint32_t a;
    asm("{ .reg .u64 t; cvta.to.shared.u64 t, %1; cvt.u32.u64 %0, t; }"
        : "=r"(a) : "l"(p));
    return a;
}
__device__ __forceinline__ uint32_t pack2(__nv_bfloat16 a, __nv_bfloat16 b) {
    return (uint32_t)__bfloat16_as_ushort(a) |
           ((uint32_t)__bfloat16_as_ushort(b) << 16);
}
__device__ __forceinline__ uint32_t pack2h(__half a, __half b) {
    return (uint32_t)__half_as_ushort(a) |
           ((uint32_t)__half_as_ushort(b) << 16);
}
__device__ __forceinline__ void split(float v, __nv_bfloat16& h, __nv_bfloat16& l) {
    h = __float2bfloat16(v);
    l = __float2bfloat16(v - __bfloat162float(h));
}

#define LDSM4(R, a) \
    asm volatile("ldmatrix.sync.aligned.m8n8.x4.shared.b16 {%0,%1,%2,%3}, [%4];" \
        : "=r"((R)[0]), "=r"((R)[1]), "=r"((R)[2]), "=r"((R)[3]) : "r"(a))

__device__ __forceinline__ void mma_bf(float* d, const uint32_t* a,
                                       const uint32_t* b) {
    asm volatile(
        "mma.sync.aligned.m16n8k16.row.col.f32.bf16.bf16.f32 "
        "{%0,%1,%2,%3}, {%4,%5,%6,%7}, {%8,%9}, {%0,%1,%2,%3};"
        : "+f"(d[0]), "+f"(d[1]), "+f"(d[2]), "+f"(d[3])
        : "r"(a[0]), "r"(a[1]), "r"(a[2]), "r"(a[3]), "r"(b[0]), "r"(b[1]));
}
__device__ __forceinline__ void mma_h(float* d, const uint32_t* a,
                                      const uint32_t* b) {
    asm volatile(
        "mma.sync.aligned.m16n8k16.row.col.f32.f16.f16.f32 "
        "{%0,%1,%2,%3}, {%4,%5,%6,%7}, {%8,%9}, {%0,%1,%2,%3};"
        : "+f"(d[0]), "+f"(d[1]), "+f"(d[2]), "+f"(d[3])
        : "r"(a[0]), "r"(a[1]), "r"(a[2]), "r"(a[3]), "r"(b[0]), "r"(b[1]));
}

// smem: NMAT matrices of 128 rows x 32 halves (64B) padded to 80B rows.
#define ROWB   80
#define MATB   10240
#define THREADS 512
#define SM_BYTES4 (2 * 4 * MATB)   // 81920 (split path)
#define SM_BYTES2 (2 * 2 * MATB)   // 40960 (fp16 path)

// ============================================================
// GEMM via mma.sync + ldmatrix. 16 warps, warp tile 32m x 32n.
// NMAT=4: split-bf16 3-term (Ah,Al,Bh,Bl). NMAT=2: single fp16 (A,B).
// OUTM: 0 = fp32[+bias/res], 1 = split bf16 hi/lo, 2 = fp16.
// Ctile(128x128) = A(MxK) . B(NxK)^T ; K-major 16-bit; K % 32 == 0.
// ============================================================
template<int NMAT, int OUTM, bool BROW, bool BCOL, bool RES>
__device__ __forceinline__ void tgemm(
    const void* __restrict__ Ah_, const void* __restrict__ Al_, int lda,
    const void* __restrict__ Bh_, const void* __restrict__ Bl_, int ldb,
    int K, float alpha,
    const float* __restrict__ bias_row, const float* __restrict__ bias_col,
    const float* __restrict__ res, int ldr,
    float* __restrict__ Cf,
    void* __restrict__ Chi, void* __restrict__ Clo, int ldc)
{
    extern __shared__ char smem[];
    const uint32_t sb = smem_u32(smem);
    const int tid  = threadIdx.x;
    const int wid  = tid >> 5, lane = tid & 31;
    const int mw   = wid >> 2, nw = wid & 3;          // 4x4 warp grid
    const int m0   = blockIdx.y * 128, n0 = blockIdx.x * 128;
    const int C    = K >> 5;
    const int STAGE = NMAT * MATB;

    const uint16_t* Ah = (const uint16_t*)Ah_;
    const uint16_t* Al = (const uint16_t*)Al_;
    const uint16_t* Bh = (const uint16_t*)Bh_;
    const uint16_t* Bl = (const uint16_t*)Bl_;

    float acc[2][4][4];
    #pragma unroll
    for (int i = 0; i < 2; i++)
        #pragma unroll
        for (int j = 0; j < 4; j++)
            #pragma unroll
            for (int q = 0; q < 4; q++) acc[i][j][q] = 0.f;

    auto load_chunk = [&](int ck) {
        const uint32_t stage = sb + (ck & 1) * STAGE;
        #pragma unroll
        for (int i = 0; i < NMAT; i++) {
            const int unit = tid + THREADS * i;       // NMAT*512 units of 16B
            const int mat = unit >> 9;
            const int row = (unit >> 2) & 127;
            const int u   = unit & 3;
            const uint16_t* src;
            if (NMAT == 4)
                src = (mat == 0) ? Ah : (mat == 1) ? Al : (mat == 2) ? Bh : Bl;
            else
                src = (mat == 0) ? Ah : Bh;
            const int ld_ = (mat < NMAT / 2) ? lda : ldb;
            const int r0  = (mat < NMAT / 2) ? m0  : n0;
            const char* gsrc =
                (const char*)(src + (size_t)(r0 + row) * ld_ + ck * 32) + u * 16;
            const uint32_t dst = stage + mat * MATB + row * ROWB + u * 16;
            asm volatile("cp.async.cg.shared.global [%0], [%1], 16;"
                         :: "r"(dst), "l"(gsrc));
        }
        asm volatile("cp.async.commit_group;" ::: "memory");
    };

    load_chunk(0);

    const int gq = lane >> 2, qt = lane & 3;
    const int lnA_row = lane & 15;
    const int lnA_off = (lane >> 4) << 4;
    const int lnB_row = (lane & 7) + ((lane & 16) >> 1);
    const int lnB_off = (lane & 8) << 1;
    const uint32_t bbase_off = (NMAT / 2) * MATB;

    for (int c = 0; c < C; c++) {
        if (c + 1 < C) load_chunk(c + 1);
        if (c + 1 < C) asm volatile("cp.async.wait_group 1;" ::: "memory");
        else           asm volatile("cp.async.wait_group 0;" ::: "memory");
        __syncthreads();

        const uint32_t stage = sb + (c & 1) * STAGE;

        #pragma unroll
        for (int ks = 0; ks < 2; ks++) {
            const uint32_t ko = ks * 32;

            uint32_t ah[2][4], al[2][4];
            #pragma unroll
            for (int mt = 0; mt < 2; mt++) {
                const uint32_t aAddr = stage +
                    (mw * 32 + mt * 16 + lnA_row) * ROWB + ko + lnA_off;
                LDSM4(ah[mt], aAddr);
                if (NMAT == 4) LDSM4(al[mt], aAddr + MATB);
            }

            #pragma unroll
            for (int p = 0; p < 2; p++) {
                const uint32_t bAddr = stage + bbase_off +
                    (nw * 32 + p * 16 + lnB_row) * ROWB + ko + lnB_off;
                uint32_t bh[4], bl[4];
                LDSM4(bh, bAddr);
                if (NMAT == 4) LDSM4(bl, bAddr + MATB);
                #pragma unroll
                for (int half = 0; half < 2; half++) {
                    const int nt = p * 2 + half;
                    #pragma unroll
                    for (int mt = 0; mt < 2; mt++) {
                        if (NMAT == 4) {
                            mma_bf(acc[mt][nt], ah[mt], bh + half * 2);
                            mma_bf(acc[mt][nt], ah[mt], bl + half * 2);
                            mma_bf(acc[mt][nt], al[mt], bh + half * 2);
                        } else {
                            mma_h(acc[mt][nt], ah[mt], bh + half * 2);
                        }
                    }
                }
            }
        }
        __syncthreads();
    }

    // ---- epilogue ----
    #pragma unroll
    for (int mt = 0; mt < 2; mt++) {
        const int mA = m0 + mw * 32 + mt * 16 + gq;
        #pragma unroll
        for (int half = 0; half < 2; half++) {
            const int m = mA + half * 8;
            const float br = BROW ? bias_row[m] : 0.f;
            #pragma unroll
            for (int nt = 0; nt < 4; nt++) {
                const int n = n0 + nw * 32 + nt * 8 + qt * 2;
                float vx = acc[mt][nt][half * 2 + 0] * alpha + br;
                float vy = acc[mt][nt][half * 2 + 1] * alpha + br;
                if (BCOL) { vx += bias_col[n]; vy += bias_col[n + 1]; }
                if (RES) {
                    const float* rp = res + (size_t)m * ldr + n;
                    vx += rp[0]; vy += rp[1];
                }
                if (OUTM == 0) {
                    float2 o = {vx, vy};
                    *(float2*)(Cf + (size_t)m * ldc + n) = o;
                } else if (OUTM == 1) {
                    __nv_bfloat16 h0, h1, l0, l1;
                    split(vx, h0, l0); split(vy, h1, l1);
                    *(uint32_t*)((__nv_bfloat16*)Chi + (size_t)m * ldc + n) = pack2(h0, h1);
                    *(uint32_t*)((__nv_bfloat16*)Clo + (size_t)m * ldc + n) = pack2(l0, l1);
                } else {
                    *(uint32_t*)((__half*)Chi + (size_t)m * ldc + n) =
                        pack2h(__float2half(vx), __float2half(vy));
                }
            }
        }
    }
}

// ================= wrapper kernels =================

// q/k: split-bf16 in, fp16 out.  z = b*2 + s
__global__ __launch_bounds__(THREADS, 1) void tg_qk(
    const float* __restrict__ bq, const float* __restrict__ bk)
{
    const int b = blockIdx.z >> 1, s = blockIdx.z & 1;
    __half* Cq = (s == 0 ? g_q16 : g_k16) + (size_t)b * HW * CH;
    tgemm<4, 2, false, true, false>(
        g_xnT_h + (size_t)b * HW * CH, g_xnT_l + (size_t)b * HW * CH, CH,
        g_w_h + (size_t)s * CH * CH, g_w_l + (size_t)s * CH * CH, CH,
        CH, 1.f, nullptr, (s == 0 ? bq : bk), nullptr, 0,
        nullptr, Cq, nullptr, CH);
}

// v: split-bf16 in, fp16 out, (c,i) layout
__global__ __launch_bounds__(THREADS, 1) void tg_v(const float* __restrict__ bv)
{
    const int b = blockIdx.z;
    tgemm<4, 2, true, false, false>(
        g_w_h + (size_t)2 * CH * CH, g_w_l + (size_t)2 * CH * CH, CH,
        g_xnT_h + (size_t)b * HW * CH, g_xnT_l + (size_t)b * HW * CH, CH,
        CH, 1.f, bv, nullptr, nullptr, 0,
        nullptr, g_v16 + (size_t)b * CH * HW, nullptr, HW);
}

// S = alpha * q16 . k16^T   (fp16 single-pass)
__global__ __launch_bounds__(THREADS, 1) void tg_score()
{
    const int b = blockIdx.z;
    tgemm<2, 0, false, false, false>(
        g_q16 + (size_t)b * HW * CH, nullptr, CH,
        g_k16 + (size_t)b * HW * CH, nullptr, CH,
        CH, 0.044194173824159216f, nullptr, nullptr, nullptr, 0,
        g_s + (size_t)b * HW * HW, nullptr, nullptr, HW);
}

// Ot = P16 . v16^T  (fp16 single-pass, split-bf16 out)
__global__ __launch_bounds__(THREADS, 1) void tg_av()
{
    const int b = blockIdx.z;
    tgemm<2, 1, false, false, false>(
        g_P16 + (size_t)b * HW * HW, nullptr, HW,
        g_v16 + (size_t)b * CH * HW, nullptr, HW,
        HW, 1.f, nullptr, nullptr, nullptr, 0,
        nullptr, g_ot_h + (size_t)b * HW * CH, g_ot_l + (size_t)b * HW * CH, CH);
}

// out = Wo . Ot^T + bo + x  (split-bf16, fp32 out + residual)
__global__ __launch_bounds__(THREADS, 1) void tg_out(
    const float* __restrict__ bo, const float* __restrict__ x,
    float* __restrict__ out)
{
    const int b = blockIdx.z;
    tgemm<4, 0, true, false, true>(
        g_w_h + (size_t)3 * CH * CH, g_w_l + (size_t)3 * CH * CH, CH,
        g_ot_h + (size_t)b * HW * CH, g_ot_l + (size_t)b * HW * CH, CH,
        CH, 1.f, bo, nullptr, x + (size_t)b * SFE, HW,
        out + (size_t)b * SFE, nullptr, nullptr, HW);
}

// ================= GroupNorm =================
__global__ __launch_bounds__(256) void gn_kernel(
    const float* __restrict__ x, const float* __restrict__ gamma,
    const float* __restrict__ beta)
{
    const int bg = blockIdx.x;
    const int CPG = CH / NG;
    const size_t base = (size_t)bg * CPG * HW;
    const int n = CPG * HW;
    const float4* xv = (const float4*)(x + base);
    float4* yv = (float4*)(g_xn + base);
    const int t = threadIdx.x;

    float s = 0.f, ss = 0.f;
    for (int i = t; i < n / 4; i += 256) {
        float4 v = xv[i];
        s  += v.x + v.y + v.z + v.w;
        ss += v.x*v.x + v.y*v.y + v.z*v.z + v.w*v.w;
    }
    __shared__ float sh[64];
    #pragma unroll
    for (int o = 16; o > 0; o >>= 1) {
        s  += __shfl_xor_sync(~0u, s, o);
        ss += __shfl_xor_sync(~0u, ss, o);
    }
    const int warp = t >> 5, lane = t & 31;
    if (lane == 0) { sh[warp] = s; sh[32 + warp] = ss; }
    __syncthreads();
    if (warp == 0) {
        float a = (lane < 8) ? sh[lane] : 0.f;
        float b = (lane < 8) ? sh[32 + lane] : 0.f;
        #pragma unroll
        for (int o = 4; o > 0; o >>= 1) {
            a += __shfl_xor_sync(~0u, a, o);
            b += __shfl_xor_sync(~0u, b, o);
        }
        if (lane == 0) { sh[0] = a; sh[1] = b; }
    }
    __syncthreads();
    const float mean = sh[0] / n;
    const float var  = sh[1] / n - mean * mean;
    const float inv  = rsqrtf(var + 1e-6f);
    const int gbase = (bg % NG) * CPG;

    for (int i = t; i < n / 4; i += 256) {
        int ch = i / (HW / 4);
        float ga = gamma[gbase + ch] * inv;
        float be = beta[gbase + ch];
        float4 v = xv[i];
        v.x = (v.x - mean) * ga + be;
        v.y = (v.y - mean) * ga + be;
        v.z = (v.z - mean) * ga + be;
        v.w = (v.w - mean) * ga + be;
        yv[i] = v;
    }
}

// ================= transpose + split =================
__global__ __launch_bounds__(256) void xpose_kernel()
{
    __shared__ float t[32][33];
    const int b = blockIdx.z;
    const int i0 = blockIdx.x * 32, c0 = blockIdx.y * 32;
    const int tx = threadIdx.x & 31, ty = threadIdx.x >> 5;
    const float* src = g_xn + (size_t)b * SFE;
    #pragma unroll
    for (int j = 0; j < 4; j++)
        t[ty + 8*j][tx] = src[(size_t)(c0 + ty + 8*j) * HW + i0 + tx];
    __syncthreads();
    #pragma unroll
    for (int j = 0; j < 4; j++) {
        float v = t[tx][ty + 8*j];
        __nv_bfloat16 h, l; split(v, h, l);
        size_t d = (size_t)b * HW * CH + (size_t)(i0 + ty + 8*j) * CH + c0 + tx;
        g_xnT_h[d] = h; g_xnT_l[d] = l;
    }
}

// ================= weight split =================
__global__ __launch_bounds__(256) void wconv_kernel(
    const float* __restrict__ wq, const float* __restrict__ wk,
    const float* __restrict__ wv, const float* __restrict__ wo)
{
    const size_t idx = (size_t)blockIdx.x * 256 + threadIdx.x;
    const int which = (int)(idx >> 18);
    const size_t off = idx & ((1 << 18) - 1);
    const float* w = (which == 0) ? wq : (which == 1) ? wk : (which == 2) ? wv : wo;
    __nv_bfloat16 h, l; split(w[off], h, l);
    g_w_h[idx] = h; g_w_l[idx] = l;
}

// ================= softmax -> P fp16 =================
__global__ __launch_bounds__(256) void softmax_kernel()
{
    const size_t row = blockIdx.x;
    const float4* pv = (const float4*)(g_s + row * HW);
    __half* ph = g_P16 + row * HW;
    const int t = threadIdx.x;
    float4 v[4];
    float mx = -1e30f;
    #pragma unroll
    for (int j = 0; j < 4; j++) {
        v[j] = pv[t + 256 * j];
        mx = fmaxf(mx, fmaxf(fmaxf(v[j].x, v[j].y), fmaxf(v[j].z, v[j].w)));
    }
    __shared__ float sh[8];
    #pragma unroll
    for (int o = 16; o > 0; o >>= 1) mx = fmaxf(mx, __shfl_xor_sync(~0u, mx, o));
    if ((t & 31) == 0) sh[t >> 5] = mx;
    __syncthreads();
    const float m0 = fmaxf(fmaxf(fmaxf(sh[0], sh[1]), fmaxf(sh[2], sh[3])),
                           fmaxf(fmaxf(sh[4], sh[5]), fmaxf(sh[6], sh[7])));
    __syncthreads();
    float sum = 0.f;
    #pragma unroll
    for (int j = 0; j < 4; j++) {
        v[j].x = __expf(v[j].x - m0);
        v[j].y = __expf(v[j].y - m0);
        v[j].z = __expf(v[j].z - m0);
        v[j].w = __expf(v[j].w - m0);
        sum += v[j].x + v[j].y + v[j].z + v[j].w;
    }
    #pragma unroll
    for (int o = 16; o > 0; o >>= 1) sum += __shfl_xor_sync(~0u, sum, o);
    if ((t & 31) == 0) sh[t >> 5] = sum;
    __syncthreads();
    const float tot = sh[0]+sh[1]+sh[2]+sh[3]+sh[4]+sh[5]+sh[6]+sh[7];
    const float inv = 1.f / tot;
    #pragma unroll
    for (int j = 0; j < 4; j++) {
        float4 e = v[j];
        e.x *= inv; e.y *= inv; e.z *= inv; e.w *= inv;
        const int eo = (t + 256 * j) * 4;
        uint2 hv = { pack2h(__float2half(e.x), __float2half(e.y)),
                     pack2h(__float2half(e.z), __float2half(e.w)) };
        *(uint2*)(ph + eo) = hv;
    }
}

// ============================================================
extern "C" void kernel_launch(void* const* d_in, const int* in_sizes, int n_in,
                              void* d_out, int out_size)
{
    const float* x   = (const float*)d_in[0];
    const float* gnw = (const float*)d_in[1];
    const float* gnb = (const float*)d_in[2];
    const float* wq  = (const float*)d_in[3];
    const float* bq  = (const float*)d_in[4];
    const float* wk  = (const float*)d_in[5];
    const float* bk  = (const float*)d_in[6];
    const float* wv  = (const float*)d_in[7];
    const float* bv  = (const float*)d_in[8];
    const float* wo  = (const float*)d_in[9];
    const float* bo  = (const float*)d_in[10];
    float* out = (float*)d_out;

    cudaFuncSetAttribute(tg_qk,  cudaFuncAttributeMaxDynamicSharedMemorySize, SM_BYTES4);
    cudaFuncSetAttribute(tg_v,   cudaFuncAttributeMaxDynamicSharedMemorySize, SM_BYTES4);
    cudaFuncSetAttribute(tg_out, cudaFuncAttributeMaxDynamicSharedMemorySize, SM_BYTES4);

    gn_kernel<<<BATCH * NG, 256>>>(x, gnw, gnb);

    dim3 gx(HW / 32, CH / 32, BATCH);
    xpose_kernel<<<gx, 256>>>();

    wconv_kernel<<<4 * CH * CH / 256, 256>>>(wq, wk, wv, wo);

    dim3 gqk(CH / 128, HW / 128, BATCH * 2);
    tg_qk<<<gqk, THREADS, SM_BYTES4>>>(bq, bk);

    dim3 gv(HW / 128, CH / 128, BATCH);
    tg_v<<<gv, THREADS, SM_BYTES4>>>(bv);

    dim3 gs(HW / 128, HW / 128, BATCH);
    tg_score<<<gs, THREADS, SM_BYTES2>>>();

    softmax_kernel<<<BATCH * HW, 256>>>();

    dim3 ga(CH / 128, HW / 128, BATCH);
    tg_av<<<ga, THREADS, SM_BYTES2>>>();

    dim3 go(HW / 128, CH / 128, BATCH);
    tg_out<<<go, THREADS, SM_BYTES4>>>(bo, x, out);
}

// round 11
// speedup vs baseline: 2.2270x; 1.2679x over previous
#include <cuda_runtime.h>
#include <cuda_fp16.h>
#include <cstdint>
#include <math.h>

#define BATCH 4
#define CH    512
#define HW    4096
#define NG    32

static const size_t SFE = (size_t)CH * HW;

// ================= scratch (device globals) =================
__device__ float  g_xn [(size_t)BATCH * CH * HW];
__device__ __half g_xnT[(size_t)BATCH * HW * CH];   // (i,c) fp16
__device__ __half g_q16[(size_t)BATCH * HW * CH];   // (i,c)
__device__ __half g_k16[(size_t)BATCH * HW * CH];   // (i,c)
__device__ __half g_v16[(size_t)BATCH * CH * HW];   // (c,i)
__device__ __half g_s16[(size_t)BATCH * HW * HW];   // scores fp16
__device__ __half g_P16[(size_t)BATCH * HW * HW];   // probs fp16
__device__ __half g_ot [(size_t)BATCH * HW * CH];   // (i,c)
__device__ __half g_w16[(size_t)4 * CH * CH];       // q,k,v,o weights

// ================= helpers =================
__device__ __forceinline__ uint32_t smem_u32(const void* p) {
    uint32_t a;
    asm("{ .reg .u64 t; cvta.to.shared.u64 t, %1; cvt.u32.u64 %0, t; }"
        : "=r"(a) : "l"(p));
    return a;
}
__device__ __forceinline__ uint32_t pack2h(__half a, __half b) {
    return (uint32_t)__half_as_ushort(a) |
           ((uint32_t)__half_as_ushort(b) << 16);
}

#define LDSM4(R, a) \
    asm volatile("ldmatrix.sync.aligned.m8n8.x4.shared.b16 {%0,%1,%2,%3}, [%4];" \
        : "=r"((R)[0]), "=r"((R)[1]), "=r"((R)[2]), "=r"((R)[3]) : "r"(a))

__device__ __forceinline__ void mma_h(float* d, const uint32_t* a,
                                      const uint32_t* b) {
    asm volatile(
        "mma.sync.aligned.m16n8k16.row.col.f32.f16.f16.f32 "
        "{%0,%1,%2,%3}, {%4,%5,%6,%7}, {%8,%9}, {%0,%1,%2,%3};"
        : "+f"(d[0]), "+f"(d[1]), "+f"(d[2]), "+f"(d[3])
        : "r"(a[0]), "r"(a[1]), "r"(a[2]), "r"(a[3]), "r"(b[0]), "r"(b[1]));
}

// smem: 2 matrices (A, B) of 128 rows x 32 halves padded to 80B rows; 2 stages.
#define ROWB   80
#define MATB   10240
#define STAGEB (2 * MATB)
#define SM_BYTES (2 * STAGEB)
#define THREADS 512

// ============================================================
// fp16 GEMM via mma.sync + ldmatrix. 16 warps, warp tile 32m x 32n.
// OUTM: 0 = fp32 [+bias/res], 2 = fp16.
// Ctile(128x128) = A(MxK) . B(NxK)^T ; K-major fp16; K % 32 == 0.
// ============================================================
template<int OUTM, bool BROW, bool BCOL, bool RES>
__device__ __forceinline__ void tgemm(
    const __half* __restrict__ A, int lda,
    const __half* __restrict__ B, int ldb,
    int K, float alpha,
    const float* __restrict__ bias_row, const float* __restrict__ bias_col,
    const float* __restrict__ res, int ldr,
    float* __restrict__ Cf, __half* __restrict__ Ch, int ldc)
{
    extern __shared__ char smem[];
    const uint32_t sb = smem_u32(smem);
    const int tid  = threadIdx.x;
    const int wid  = tid >> 5, lane = tid & 31;
    const int mw   = wid >> 2, nw = wid & 3;
    const int m0   = blockIdx.y * 128, n0 = blockIdx.x * 128;
    const int C    = K >> 5;

    float acc[2][4][4];
    #pragma unroll
    for (int i = 0; i < 2; i++)
        #pragma unroll
        for (int j = 0; j < 4; j++)
            #pragma unroll
            for (int q = 0; q < 4; q++) acc[i][j][q] = 0.f;

    auto load_chunk = [&](int ck) {
        const uint32_t stage = sb + (ck & 1) * STAGEB;
        #pragma unroll
        for (int i = 0; i < 2; i++) {
            const int unit = tid + THREADS * i;       // 1024 units of 16B
            const int mat = unit >> 9;
            const int row = (unit >> 2) & 127;
            const int u   = unit & 3;
            const __half* src = (mat == 0) ? A : B;
            const int ld_ = (mat == 0) ? lda : ldb;
            const int r0  = (mat == 0) ? m0  : n0;
            const char* gsrc =
                (const char*)(src + (size_t)(r0 + row) * ld_ + ck * 32) + u * 16;
            const uint32_t dst = stage + mat * MATB + row * ROWB + u * 16;
            asm volatile("cp.async.cg.shared.global [%0], [%1], 16;"
                         :: "r"(dst), "l"(gsrc));
        }
        asm volatile("cp.async.commit_group;" ::: "memory");
    };

    load_chunk(0);

    const int gq = lane >> 2, qt = lane & 3;
    const int lnA_row = lane & 15;
    const int lnA_off = (lane >> 4) << 4;
    const int lnB_row = (lane & 7) + ((lane & 16) >> 1);
    const int lnB_off = (lane & 8) << 1;

    for (int c = 0; c < C; c++) {
        if (c + 1 < C) load_chunk(c + 1);
        if (c + 1 < C) asm volatile("cp.async.wait_group 1;" ::: "memory");
        else           asm volatile("cp.async.wait_group 0;" ::: "memory");
        __syncthreads();

        const uint32_t stage = sb + (c & 1) * STAGEB;

        #pragma unroll
        for (int ks = 0; ks < 2; ks++) {
            const uint32_t ko = ks * 32;

            uint32_t ah[2][4];
            #pragma unroll
            for (int mt = 0; mt < 2; mt++) {
                const uint32_t aAddr = stage +
                    (mw * 32 + mt * 16 + lnA_row) * ROWB + ko + lnA_off;
                LDSM4(ah[mt], aAddr);
            }

            #pragma unroll
            for (int p = 0; p < 2; p++) {
                const uint32_t bAddr = stage + MATB +
                    (nw * 32 + p * 16 + lnB_row) * ROWB + ko + lnB_off;
                uint32_t bh[4];
                LDSM4(bh, bAddr);
                #pragma unroll
                for (int half_ = 0; half_ < 2; half_++) {
                    const int nt = p * 2 + half_;
                    #pragma unroll
                    for (int mt = 0; mt < 2; mt++)
                        mma_h(acc[mt][nt], ah[mt], bh + half_ * 2);
                }
            }
        }
        __syncthreads();
    }

    // ---- epilogue ----
    #pragma unroll
    for (int mt = 0; mt < 2; mt++) {
        const int mA = m0 + mw * 32 + mt * 16 + gq;
        #pragma unroll
        for (int half_ = 0; half_ < 2; half_++) {
            const int m = mA + half_ * 8;
            const float br = BROW ? bias_row[m] : 0.f;
            #pragma unroll
            for (int nt = 0; nt < 4; nt++) {
                const int n = n0 + nw * 32 + nt * 8 + qt * 2;
                float vx = acc[mt][nt][half_ * 2 + 0] * alpha + br;
                float vy = acc[mt][nt][half_ * 2 + 1] * alpha + br;
                if (BCOL) { vx += bias_col[n]; vy += bias_col[n + 1]; }
                if (RES) {
                    const float* rp = res + (size_t)m * ldr + n;
                    vx += rp[0]; vy += rp[1];
                }
                if (OUTM == 0) {
                    float2 o = {vx, vy};
                    *(float2*)(Cf + (size_t)m * ldc + n) = o;
                } else {
                    *(uint32_t*)(Ch + (size_t)m * ldc + n) =
                        pack2h(__float2half(vx), __float2half(vy));
                }
            }
        }
    }
}

// ================= wrapper kernels =================

// q/k: z = b*2 + s
__global__ __launch_bounds__(THREADS, 1) void tg_qk(
    const float* __restrict__ bq, const float* __restrict__ bk)
{
    const int b = blockIdx.z >> 1, s = blockIdx.z & 1;
    __half* Cq = (s == 0 ? g_q16 : g_k16) + (size_t)b * HW * CH;
    tgemm<2, false, true, false>(
        g_xnT + (size_t)b * HW * CH, CH,
        g_w16 + (size_t)s * CH * CH, CH,
        CH, 1.f, nullptr, (s == 0 ? bq : bk), nullptr, 0,
        nullptr, Cq, CH);
}

// v: (c,i) layout
__global__ __launch_bounds__(THREADS, 1) void tg_v(const float* __restrict__ bv)
{
    const int b = blockIdx.z;
    tgemm<2, true, false, false>(
        g_w16 + (size_t)2 * CH * CH, CH,
        g_xnT + (size_t)b * HW * CH, CH,
        CH, 1.f, bv, nullptr, nullptr, 0,
        nullptr, g_v16 + (size_t)b * CH * HW, HW);
}

// S = alpha * q16 . k16^T  -> fp16
__global__ __launch_bounds__(THREADS, 1) void tg_score()
{
    const int b = blockIdx.z;
    tgemm<2, false, false, false>(
        g_q16 + (size_t)b * HW * CH, CH,
        g_k16 + (size_t)b * HW * CH, CH,
        CH, 0.044194173824159216f, nullptr, nullptr, nullptr, 0,
        nullptr, g_s16 + (size_t)b * HW * HW, HW);
}

// Ot = P16 . v16^T -> fp16 (i,c)
__global__ __launch_bounds__(THREADS, 1) void tg_av()
{
    const int b = blockIdx.z;
    tgemm<2, false, false, false>(
        g_P16 + (size_t)b * HW * HW, HW,
        g_v16 + (size_t)b * CH * HW, HW,
        HW, 1.f, nullptr, nullptr, nullptr, 0,
        nullptr, g_ot + (size_t)b * HW * CH, CH);
}

// out = Wo . Ot^T + bo + x  (fp32 out + residual)
__global__ __launch_bounds__(THREADS, 1) void tg_out(
    const float* __restrict__ bo, const float* __restrict__ x,
    float* __restrict__ out)
{
    const int b = blockIdx.z;
    tgemm<0, true, false, true>(
        g_w16 + (size_t)3 * CH * CH, CH,
        g_ot + (size_t)b * HW * CH, CH,
        CH, 1.f, bo, nullptr, x + (size_t)b * SFE, HW,
        out + (size_t)b * SFE, nullptr, HW);
}

// ================= GroupNorm =================
__global__ __launch_bounds__(256) void gn_kernel(
    const float* __restrict__ x, const float* __restrict__ gamma,
    const float* __restrict__ beta)
{
    const int bg = blockIdx.x;
    const int CPG = CH / NG;
    const size_t base = (size_t)bg * CPG * HW;
    const int n = CPG * HW;
    const float4* xv = (const float4*)(x + base);
    float4* yv = (float4*)(g_xn + base);
    const int t = threadIdx.x;

    float s = 0.f, ss = 0.f;
    for (int i = t; i < n / 4; i += 256) {
        float4 v = xv[i];
        s  += v.x + v.y + v.z + v.w;
        ss += v.x*v.x + v.y*v.y + v.z*v.z + v.w*v.w;
    }
    __shared__ float sh[64];
    #pragma unroll
    for (int o = 16; o > 0; o >>= 1) {
        s  += __shfl_xor_sync(~0u, s, o);
        ss += __shfl_xor_sync(~0u, ss, o);
    }
    const int warp = t >> 5, lane = t & 31;
    if (lane == 0) { sh[warp] = s; sh[32 + warp] = ss; }
    __syncthreads();
    if (warp == 0) {
        float a = (lane < 8) ? sh[lane] : 0.f;
        float b = (lane < 8) ? sh[32 + lane] : 0.f;
        #pragma unroll
        for (int o = 4; o > 0; o >>= 1) {
            a += __shfl_xor_sync(~0u, a, o);
            b += __shfl_xor_sync(~0u, b, o);
        }
        if (lane == 0) { sh[0] = a; sh[1] = b; }
    }
    __syncthreads();
    const float mean = sh[0] / n;
    const float var  = sh[1] / n - mean * mean;
    const float inv  = rsqrtf(var + 1e-6f);
    const int gbase = (bg % NG) * CPG;

    for (int i = t; i < n / 4; i += 256) {
        int ch = i / (HW / 4);
        float ga = gamma[gbase + ch] * inv;
        float be = beta[gbase + ch];
        float4 v = xv[i];
        v.x = (v.x - mean) * ga + be;
        v.y = (v.y - mean) * ga + be;
        v.z = (v.z - mean) * ga + be;
        v.w = (v.w - mean) * ga + be;
        yv[i] = v;
    }
}

// ================= transpose to fp16 (i,c) =================
__global__ __launch_bounds__(256) void xpose_kernel()
{
    __shared__ float t[32][33];
    const int b = blockIdx.z;
    const int i0 = blockIdx.x * 32, c0 = blockIdx.y * 32;
    const int tx = threadIdx.x & 31, ty = threadIdx.x >> 5;
    const float* src = g_xn + (size_t)b * SFE;
    #pragma unroll
    for (int j = 0; j < 4; j++)
        t[ty + 8*j][tx] = src[(size_t)(c0 + ty + 8*j) * HW + i0 + tx];
    __syncthreads();
    #pragma unroll
    for (int j = 0; j < 4; j++) {
        float v = t[tx][ty + 8*j];
        size_t d = (size_t)b * HW * CH + (size_t)(i0 + ty + 8*j) * CH + c0 + tx;
        g_xnT[d] = __float2half(v);
    }
}

// ================= weight convert =================
__global__ __launch_bounds__(256) void wconv_kernel(
    const float* __restrict__ wq, const float* __restrict__ wk,
    const float* __restrict__ wv, const float* __restrict__ wo)
{
    const size_t idx = (size_t)blockIdx.x * 256 + threadIdx.x;
    const int which = (int)(idx >> 18);
    const size_t off = idx & ((1 << 18) - 1);
    const float* w = (which == 0) ? wq : (which == 1) ? wk : (which == 2) ? wv : wo;
    g_w16[idx] = __float2half(w[off]);
}

// ================= softmax: fp16 in -> fp16 out =================
__global__ __launch_bounds__(256) void softmax_kernel()
{
    const size_t row = blockIdx.x;
    const uint2* pv = (const uint2*)(g_s16 + row * HW);   // 4 halves per uint2
    __half* ph = g_P16 + row * HW;
    const int t = threadIdx.x;
    float v[4][4];
    float mx = -1e30f;
    #pragma unroll
    for (int j = 0; j < 4; j++) {
        uint2 u = pv[t + 256 * j];
        __half2 a = *(__half2*)&u.x, b = *(__half2*)&u.y;
        float2 fa = __half22float2(a), fb = __half22float2(b);
        v[j][0] = fa.x; v[j][1] = fa.y; v[j][2] = fb.x; v[j][3] = fb.y;
        mx = fmaxf(mx, fmaxf(fmaxf(v[j][0], v[j][1]), fmaxf(v[j][2], v[j][3])));
    }
    __shared__ float sh[8];
    #pragma unroll
    for (int o = 16; o > 0; o >>= 1) mx = fmaxf(mx, __shfl_xor_sync(~0u, mx, o));
    if ((t & 31) == 0) sh[t >> 5] = mx;
    __syncthreads();
    const float m0 = fmaxf(fmaxf(fmaxf(sh[0], sh[1]), fmaxf(sh[2], sh[3])),
                           fmaxf(fmaxf(sh[4], sh[5]), fmaxf(sh[6], sh[7])));
    __syncthreads();
    float sum = 0.f;
    #pragma unroll
    for (int j = 0; j < 4; j++) {
        #pragma unroll
        for (int q = 0; q < 4; q++) {
            v[j][q] = __expf(v[j][q] - m0);
            sum += v[j][q];
        }
    }
    #pragma unroll
    for (int o = 16; o > 0; o >>= 1) sum += __shfl_xor_sync(~0u, sum, o);
    if ((t & 31) == 0) sh[t >> 5] = sum;
    __syncthreads();
    const float tot = sh[0]+sh[1]+sh[2]+sh[3]+sh[4]+sh[5]+sh[6]+sh[7];
    const float inv = 1.f / tot;
    #pragma unroll
    for (int j = 0; j < 4; j++) {
        const int eo = (t + 256 * j) * 4;
        uint2 hv = { pack2h(__float2half(v[j][0] * inv), __float2half(v[j][1] * inv)),
                     pack2h(__float2half(v[j][2] * inv), __float2half(v[j][3] * inv)) };
        *(uint2*)(ph + eo) = hv;
    }
}

// ============================================================
extern "C" void kernel_launch(void* const* d_in, const int* in_sizes, int n_in,
                              void* d_out, int out_size)
{
    const float* x   = (const float*)d_in[0];
    const float* gnw = (const float*)d_in[1];
    const float* gnb = (const float*)d_in[2];
    const float* wq  = (const float*)d_in[3];
    const float* bq  = (const float*)d_in[4];
    const float* wk  = (const float*)d_in[5];
    const float* bk  = (const float*)d_in[6];
    const float* wv  = (const float*)d_in[7];
    const float* bv  = (const float*)d_in[8];
    const float* wo  = (const float*)d_in[9];
    const float* bo  = (const float*)d_in[10];
    float* out = (float*)d_out;

    gn_kernel<<<BATCH * NG, 256>>>(x, gnw, gnb);

    dim3 gx(HW / 32, CH / 32, BATCH);
    xpose_kernel<<<gx, 256>>>();

    wconv_kernel<<<4 * CH * CH / 256, 256>>>(wq, wk, wv, wo);

    dim3 gqk(CH / 128, HW / 128, BATCH * 2);
    tg_qk<<<gqk, THREADS, SM_BYTES>>>(bq, bk);

    dim3 gv(HW / 128, CH / 128, BATCH);
    tg_v<<<gv, THREADS, SM_BYTES>>>(bv);

    dim3 gs(HW / 128, HW / 128, BATCH);
    tg_score<<<gs, THREADS, SM_BYTES>>>();

    softmax_kernel<<<BATCH * HW, 256>>>();

    dim3 ga(CH / 128, HW / 128, BATCH);
    tg_av<<<ga, THREADS, SM_BYTES>>>();

    dim3 go(HW / 128, CH / 128, BATCH);
    tg_out<<<go, THREADS, SM_BYTES>>>(bo, x, out);
}